// round 6
// baseline (speedup 1.0000x reference)
#include <cuda_runtime.h>
#include <cuda_fp16.h>
#include <cstdint>

#define Bv 128
#define Tv 4096
#define DIN 64
#define Hv 512
#define DOUT 64
#define NCTA 128
#define NTHR 256
#define K1 576
#define K2 1024
#define K1PH 584            // weight row stride (halfs) -> conflict-free B-frag LDS
#define K2PH 1032
#define NCH1 9
#define NCH2 16
#define NBUF 4
#define GW 72               // chunk row stride (halfs) -> conflict-free A-frag LDS
#define CHUNK_W (128 * GW)
#define CHUNK_BYTES (CHUNK_W * 2)   // 18432
#define OW 68               // out_gemm smem stride (floats)
#define FLG 64              // flag spacing (words) = 256B -> distinct LTS slices
#define SMEM_BYTES (NBUF * CHUNK_BYTES + 32 * K2PH * 2 + 128 * 8 * 4 + 32 * 4 + 96)

// Persistent scratch (static __device__: the sanctioned allocation path)
__device__ __half g_xT[(size_t)Tv * CHUNK_W];                 // x transposed, fp16
__device__ __half g_h1[2][8][128][GW];                        // layer1 h (fp16), chunk-major
__device__ __half g_h2all[(size_t)(Tv + 1) * 8 * CHUNK_W];    // h2 history; slot 0 = zeros
__device__ unsigned g_flags[NCTA * FLG];                      // per-CTA arrival flags
__device__ unsigned g_bar_epoch;                              // monotonic across replays

__device__ __forceinline__ float sigm(float x) { return 1.0f / (1.0f + __expf(-x)); }
__device__ __forceinline__ float tanh_(float x) { return 1.0f - 2.0f / (__expf(2.0f * x) + 1.0f); }

__device__ __forceinline__ void issue_chunk(unsigned sdst, const void* gsrc, unsigned mbar) {
    asm volatile("mbarrier.arrive.expect_tx.shared.b64 _, [%0], %1;"
                 :: "r"(mbar), "r"((unsigned)CHUNK_BYTES) : "memory");
    asm volatile("cp.async.bulk.shared::cta.global.mbarrier::complete_tx::bytes [%0], [%1], %2, [%3];"
                 :: "r"(sdst), "l"(gsrc), "r"((unsigned)CHUNK_BYTES), "r"(mbar) : "memory");
}
__device__ __forceinline__ void mbar_wait(unsigned mbar, unsigned parity) {
    asm volatile(
        "{\n\t.reg .pred P;\n"
        "W%=:\n\t"
        "mbarrier.try_wait.parity.acquire.cta.shared::cta.b64 P, [%0], %1, 0x989680;\n\t"
        "@!P bra W%=;\n\t}"
        :: "r"(mbar), "r"(parity) : "memory");
}
__device__ __forceinline__ void mbar_arrive(unsigned mbar) {
    asm volatile("mbarrier.arrive.shared.b64 _, [%0];" :: "r"(mbar) : "memory");
}

// Atomic-free grid barrier: flag stores + CTA0 parallel poll + epoch publish.
__device__ __forceinline__ void gridbar(unsigned target) {
    __syncthreads();
    if (threadIdx.x == 0)
        asm volatile("st.release.gpu.global.b32 [%0], %1;"
                     :: "l"(&g_flags[blockIdx.x * FLG]), "r"(target) : "memory");
    if (blockIdx.x == 0) {
        if (threadIdx.x < NCTA) {
            const unsigned* f = &g_flags[threadIdx.x * FLG];
            unsigned v;
            do {
                asm volatile("ld.acquire.gpu.global.b32 %0, [%1];" : "=r"(v) : "l"(f));
            } while ((int)(v - target) < 0);
        }
        __syncthreads();
        if (threadIdx.x == 0)
            asm volatile("st.release.gpu.global.b32 [%0], %1;"
                         :: "l"(&g_bar_epoch), "r"(target) : "memory");
    } else {
        if (threadIdx.x == 0) {
            unsigned v;
            do {
                asm volatile("ld.acquire.gpu.global.b32 %0, [%1];" : "=r"(v) : "l"(&g_bar_epoch));
            } while ((int)(v - target) < 0);
        }
        __syncthreads();
    }
}

// One-time x transpose + fp16 round: x[b][t][64] -> xT[t][b][72-padded]
__global__ void __launch_bounds__(256)
xpose(const float* __restrict__ x) {
    const int t = blockIdx.x;
    for (int i = threadIdx.x; i < 128 * 16; i += 256) {
        int b = i >> 4, j = i & 15;
        float4 v = *(const float4*)(x + ((size_t)b * Tv + t) * 64 + j * 4);
        __half2* dst = (__half2*)(g_xT + (size_t)t * CHUNK_W + b * GW + j * 4);
        dst[0] = __floats2half2_rn(v.x, v.y);
        dst[1] = __floats2half2_rn(v.z, v.w);
    }
}

__global__ void __launch_bounds__(NTHR, 1)
lstm_kernel(const float* __restrict__ w_ih1, const float* __restrict__ w_hh1,
            const float* __restrict__ b_ih1, const float* __restrict__ b_hh1,
            const float* __restrict__ w_ih2, const float* __restrict__ w_hh2,
            const float* __restrict__ b_ih2, const float* __restrict__ b_hh2) {
    extern __shared__ __half smh[];
    __half* chunks = smh;                            // NBUF x [128][GW]
    __half* swh = smh + NBUF * CHUNK_W;              // weights fp16 [32][K1PH|K2PH]
    float* sc = (float*)(swh + 32 * K2PH);           // c-state [128][8]
    float* sb = sc + 128 * 8;                        // fused biases [32]
    float* mbf = sb + 32;                            // 8 mbarriers: full[4], consumed[4]
    __shared__ unsigned s_epoch0;

    const int tid = threadIdx.x;
    const bool isL2 = blockIdx.x >= 64;
    const int u0 = (blockIdx.x & 63) * 8;
    const int lane = tid & 31, warp = tid >> 5;
    const int c4 = lane & 3, q = lane >> 2;
    const int r0 = warp * 16 + q, r1 = r0 + 8;
    const int KPH = isL2 ? K2PH : K1PH;
    const int NCH = isL2 ? NCH2 : NCH1;
    const unsigned smem_base = (unsigned)__cvta_generic_to_shared(smh);
    const unsigned mb = (unsigned)__cvta_generic_to_shared(mbf);
    // full[b] = mb + b*8 ; consumed[b] = mb + 32 + b*8

    if (tid == 0) {
        s_epoch0 = *(volatile unsigned*)&g_bar_epoch;
#pragma unroll
        for (int b = 0; b < NBUF; b++) {
            asm volatile("mbarrier.init.shared.b64 [%0], 1;" :: "r"(mb + b * 8) : "memory");
            asm volatile("mbarrier.init.shared.b64 [%0], 8;" :: "r"(mb + 32 + b * 8) : "memory");
        }
        asm volatile("fence.proxy.async.shared::cta;" ::: "memory");
    }

    // ---- stage weight slice (fp16) + fused biases ----
    if (!isL2) {
        for (int idx = tid; idx < 32 * K1; idx += NTHR) {
            int r = idx / K1, k = idx - r * K1;
            int j = (r >> 3) * Hv + u0 + (r & 7);
            float wv = (k < DIN) ? w_ih1[j * DIN + k] : w_hh1[(size_t)j * Hv + (k - DIN)];
            swh[r * K1PH + k] = __float2half_rn(wv);
        }
        if (tid < 32) {
            int j = (tid >> 3) * Hv + u0 + (tid & 7);
            sb[tid] = b_ih1[j] + b_hh1[j];
        }
    } else {
        for (int idx = tid; idx < 32 * K2; idx += NTHR) {
            int r = idx >> 10, k = idx & 1023;
            int j = (r >> 3) * Hv + u0 + (r & 7);
            float wv = (k < Hv) ? w_ih2[(size_t)j * Hv + k] : w_hh2[(size_t)j * Hv + (k - Hv)];
            swh[r * K2PH + k] = __float2half_rn(wv);
        }
        if (tid < 32) {
            int j = (tid >> 3) * Hv + u0 + (tid & 7);
            sb[tid] = b_ih2[j] + b_hh2[j];
        }
    }
    for (int i = tid; i < 128 * 8; i += NTHR) sc[i] = 0.0f;

    // ---- zero initial shared state (h1 slot 1, h2 slot 0), as 4B words ----
    {
        unsigned* z1 = (unsigned*)&g_h1[1][0][0][0];
        unsigned* z2 = (unsigned*)g_h2all;
        const int nw = 8 * CHUNK_W / 2;
        for (int idx = blockIdx.x * NTHR + tid; idx < nw; idx += NCTA * NTHR) {
            z1[idx] = 0u;
            z2[idx] = 0u;
        }
    }
    __syncthreads();
    unsigned bar = s_epoch0;
    gridbar(++bar);

    unsigned phbits = 0;
    unsigned nb[NBUF] = {0, 0, 0, 0};    // per-buffer wave counters (tid0 only)
    const int ch = u0 >> 6, colbase = u0 & 63;

    for (int p = 0; p <= Tv; p++) {
        const bool active = isL2 ? (p >= 1) : (p < Tv);
        if (active) {
            const __half* srcA;
            const __half* srcB;
            if (isL2) {
                srcA = &g_h1[(p - 1) & 1][0][0][0];
                srcB = g_h2all + (size_t)(p - 1) * 8 * CHUNK_W;
            } else {
                srcA = g_xT + (size_t)p * CHUNK_W;
                srcB = &g_h1[(p - 1) & 1][0][0][0];
            }
            auto csrc = [&](int c) -> const __half* {
                if (!isL2) return (c == 0) ? srcA : srcB + (size_t)(c - 1) * CHUNK_W;
                return (c < 8) ? srcA + (size_t)c * CHUNK_W : srcB + (size_t)(c - 8) * CHUNK_W;
            };

            float acc[4][4];
#pragma unroll
            for (int g = 0; g < 4; g++) {
                float b0 = sb[g * 8 + 2 * c4], b1 = sb[g * 8 + 2 * c4 + 1];
                acc[g][0] = b0; acc[g][1] = b1; acc[g][2] = b0; acc[g][3] = b1;
            }

            if (tid == 0) {   // prologue: buffers guaranteed free (all consumed pre-gridbar)
                for (int c = 0; c < NBUF; c++)
                    issue_chunk(smem_base + c * CHUNK_BYTES, csrc(c), mb + c * 8);
            }

#pragma unroll 4
            for (int c = 0; c < NCH; c++) {
                const int bsel = c & 3;
                mbar_wait(mb + bsel * 8, (phbits >> bsel) & 1u);
                phbits ^= (1u << bsel);

                const __half* ar0 = chunks + bsel * CHUNK_W + r0 * GW + 2 * c4;
                const __half* ar1 = chunks + bsel * CHUNK_W + r1 * GW + 2 * c4;
                const int kb = c * 64;
#pragma unroll
                for (int kc = 0; kc < 64; kc += 16) {
                    unsigned a0 = *(const unsigned*)(ar0 + kc);
                    unsigned a1 = *(const unsigned*)(ar1 + kc);
                    unsigned a2 = *(const unsigned*)(ar0 + kc + 8);
                    unsigned a3 = *(const unsigned*)(ar1 + kc + 8);
#pragma unroll
                    for (int g = 0; g < 4; g++) {
                        const __half* bp = swh + (g * 8 + q) * KPH + kb + kc + 2 * c4;
                        unsigned b0 = *(const unsigned*)bp;
                        unsigned b1 = *(const unsigned*)(bp + 8);
                        asm volatile(
                            "mma.sync.aligned.m16n8k16.row.col.f32.f16.f16.f32 "
                            "{%0,%1,%2,%3},{%4,%5,%6,%7},{%8,%9},{%0,%1,%2,%3};"
                            : "+f"(acc[g][0]), "+f"(acc[g][1]), "+f"(acc[g][2]), "+f"(acc[g][3])
                            : "r"(a0), "r"(a1), "r"(a2), "r"(a3), "r"(b0), "r"(b1));
                    }
                }
                if (lane == 0) mbar_arrive(mb + 32 + bsel * 8);   // warp done with buffer
                if (tid == 0) {
                    nb[bsel]++;
                    if (c + NBUF < NCH) {   // wait all 8 warps done, then reuse buffer
                        mbar_wait(mb + 32 + bsel * 8, (nb[bsel] - 1) & 1u);
                        issue_chunk(smem_base + bsel * CHUNK_BYTES, csrc(c + NBUF),
                                    mb + bsel * 8);
                    }
                }
            }

            // ---- epilogue: nonlinearities, c update (SMEM), fp16 h store ----
            __half* hout = isL2
                ? g_h2all + ((size_t)p * 8 + ch) * CHUNK_W + colbase
                : &g_h1[p & 1][ch][0][colbase];
#pragma unroll
            for (int jj = 0; jj < 2; jj++) {
                int ul = 2 * c4 + jj;
#pragma unroll
                for (int rr = 0; rr < 2; rr++) {
                    int row = rr ? r1 : r0;
                    int qi = rr * 2 + jj;
                    float iv = sigm(acc[0][qi]);
                    float fv = sigm(acc[1][qi]);
                    float gv = tanh_(acc[2][qi]);
                    float ov = sigm(acc[3][qi]);
                    float cn = fv * sc[row * 8 + ul] + iv * gv;
                    sc[row * 8 + ul] = cn;
                    hout[(size_t)row * GW + ul] = __float2half_rn(ov * tanh_(cn));
                }
            }
        }
        gridbar(++bar);
    }
}

// Post-pass: out[b][t][o] = h2(t)[b] . w_out[o] + b_out[o]
__global__ void __launch_bounds__(256)
out_gemm(const float* __restrict__ w_out, const float* __restrict__ b_out,
         float* __restrict__ out) {
    __shared__ __align__(16) float As[32 * OW];  // [k][t]
    __shared__ __align__(16) float Bs[32 * OW];  // [k][o]
    const int b = blockIdx.y;
    const int t0 = blockIdx.x * 64;
    const int tx = threadIdx.x;
    const int to = (tx & 15) * 4;
    const int tt = (tx >> 4) * 4;
    float acc[4][4] = {};
    for (int k0 = 0; k0 < Hv; k0 += 32) {
        for (int i = tx; i < 512; i += 256) {
            int row = i >> 3, kq = (i & 7) * 4;
            const __half* src = g_h2all + ((size_t)(t0 + row + 1) * 8 + (k0 >> 6)) * CHUNK_W
                              + (size_t)b * GW + (k0 & 63) + kq;
            float2 f0 = __half22float2(*(const __half2*)(src));
            float2 f1 = __half22float2(*(const __half2*)(src + 2));
            As[(kq + 0) * OW + row] = f0.x;
            As[(kq + 1) * OW + row] = f0.y;
            As[(kq + 2) * OW + row] = f1.x;
            As[(kq + 3) * OW + row] = f1.y;
        }
        for (int i = tx; i < 512; i += 256) {
            int o = i >> 3, kq = (i & 7) * 4;
            float4 v = *(const float4*)(w_out + (size_t)o * Hv + k0 + kq);
            Bs[(kq + 0) * OW + o] = v.x;
            Bs[(kq + 1) * OW + o] = v.y;
            Bs[(kq + 2) * OW + o] = v.z;
            Bs[(kq + 3) * OW + o] = v.w;
        }
        __syncthreads();
#pragma unroll
        for (int k = 0; k < 32; k++) {
            float4 a = *(const float4*)(As + k * OW + tt);
            float4 w = *(const float4*)(Bs + k * OW + to);
            acc[0][0] = fmaf(a.x, w.x, acc[0][0]); acc[0][1] = fmaf(a.x, w.y, acc[0][1]);
            acc[0][2] = fmaf(a.x, w.z, acc[0][2]); acc[0][3] = fmaf(a.x, w.w, acc[0][3]);
            acc[1][0] = fmaf(a.y, w.x, acc[1][0]); acc[1][1] = fmaf(a.y, w.y, acc[1][1]);
            acc[1][2] = fmaf(a.y, w.z, acc[1][2]); acc[1][3] = fmaf(a.y, w.w, acc[1][3]);
            acc[2][0] = fmaf(a.z, w.x, acc[2][0]); acc[2][1] = fmaf(a.z, w.y, acc[2][1]);
            acc[2][2] = fmaf(a.z, w.z, acc[2][2]); acc[2][3] = fmaf(a.z, w.w, acc[2][3]);
            acc[3][0] = fmaf(a.w, w.x, acc[3][0]); acc[3][1] = fmaf(a.w, w.y, acc[3][1]);
            acc[3][2] = fmaf(a.w, w.z, acc[3][2]); acc[3][3] = fmaf(a.w, w.w, acc[3][3]);
        }
        __syncthreads();
    }
    float bo0 = b_out[to + 0], bo1 = b_out[to + 1], bo2 = b_out[to + 2], bo3 = b_out[to + 3];
#pragma unroll
    for (int i = 0; i < 4; i++) {
        float4 r;
        r.x = acc[i][0] + bo0; r.y = acc[i][1] + bo1;
        r.z = acc[i][2] + bo2; r.w = acc[i][3] + bo3;
        *(float4*)(out + ((size_t)b * Tv + t0 + tt + i) * DOUT + to) = r;
    }
}

extern "C" void kernel_launch(void* const* d_in, const int* in_sizes, int n_in,
                              void* d_out, int out_size) {
    (void)in_sizes; (void)n_in; (void)out_size;
    const float* x     = (const float*)d_in[0];
    const float* w_ih1 = (const float*)d_in[1];
    const float* w_hh1 = (const float*)d_in[2];
    const float* b_ih1 = (const float*)d_in[3];
    const float* b_hh1 = (const float*)d_in[4];
    const float* w_ih2 = (const float*)d_in[5];
    const float* w_hh2 = (const float*)d_in[6];
    const float* b_ih2 = (const float*)d_in[7];
    const float* b_hh2 = (const float*)d_in[8];
    const float* w_out = (const float*)d_in[9];
    const float* b_out = (const float*)d_in[10];

    xpose<<<Tv, 256>>>(x);
    cudaFuncSetAttribute(lstm_kernel, cudaFuncAttributeMaxDynamicSharedMemorySize, SMEM_BYTES);
    lstm_kernel<<<NCTA, NTHR, SMEM_BYTES>>>(w_ih1, w_hh1, b_ih1, b_hh1,
                                            w_ih2, w_hh2, b_ih2, b_hh2);
    out_gemm<<<dim3(Tv / 64, Bv), 256>>>(w_out, b_out, (float*)d_out);
}

// round 8
// speedup vs baseline: 1.0296x; 1.0296x over previous
#include <cuda_runtime.h>
#include <cuda_fp16.h>
#include <cstdint>

#define Bv 128
#define Tv 4096
#define DIN 64
#define Hv 512
#define DOUT 64
#define NCTA 128
#define NTHR 256
#define K1 576
#define K2 1024
#define K1PH 584            // weight row stride (halfs) -> conflict-free B-frag LDS
#define K2PH 1032
#define NCH1 9
#define NCH2 16
#define NBUF 8
#define GW 72               // chunk row stride (halfs) -> conflict-free A-frag LDS
#define CHUNK_W (128 * GW)
#define CHUNK_BYTES (CHUNK_W * 2)   // 18432
#define OW 68               // out_gemm smem stride (floats)
#define SMEM_BYTES (NBUF * CHUNK_BYTES + 32 * K2PH * 2 + 128 * 8 * 4 + 32 * 4 + 96)

// Persistent scratch (static __device__: the sanctioned allocation path)
__device__ __half g_xT[(size_t)Tv * CHUNK_W];                 // x transposed, fp16
__device__ __half g_h1[2][8][128][GW];                        // layer1 h (fp16), chunk-major
__device__ __half g_h2all[(size_t)(Tv + 1) * 8 * CHUNK_W];    // h2 history; slot 0 = zeros
__device__ unsigned g_cnt[8 * 64];                            // group counters, 256B-spread
__device__ unsigned g_top;                                    // top-level counter
__device__ unsigned g_bar_epoch;                              // monotonic across replays

__device__ __forceinline__ float sigm(float x) { return 1.0f / (1.0f + __expf(-x)); }
__device__ __forceinline__ float tanh_(float x) { return 1.0f - 2.0f / (__expf(2.0f * x) + 1.0f); }

__device__ __forceinline__ void issue_chunk(unsigned sdst, const void* gsrc, unsigned mbar) {
    asm volatile("mbarrier.arrive.expect_tx.shared.b64 _, [%0], %1;"
                 :: "r"(mbar), "r"((unsigned)CHUNK_BYTES) : "memory");
    asm volatile("cp.async.bulk.shared::cta.global.mbarrier::complete_tx::bytes [%0], [%1], %2, [%3];"
                 :: "r"(sdst), "l"(gsrc), "r"((unsigned)CHUNK_BYTES), "r"(mbar) : "memory");
}
__device__ __forceinline__ void mbar_wait(unsigned mbar, unsigned parity) {
    asm volatile(
        "{\n\t.reg .pred P;\n"
        "W%=:\n\t"
        "mbarrier.try_wait.parity.acquire.cta.shared::cta.b64 P, [%0], %1, 0x989680;\n\t"
        "@!P bra W%=;\n\t}"
        :: "r"(mbar), "r"(parity) : "memory");
}

// Hierarchical monotonic grid barrier: 8 spread group counters -> top counter -> epoch.
__device__ __forceinline__ void gridbar(unsigned target) {
    __syncthreads();
    if (threadIdx.x == 0) {
        __threadfence();
        bool pub = false;
        unsigned a = atomicAdd(&g_cnt[(blockIdx.x & 7) * 64], 1u) + 1u;
        if ((a & 15u) == 0u) {
            unsigned b = atomicAdd(&g_top, 1u) + 1u;
            if ((b & 7u) == 0u) {
                __threadfence();
                *(volatile unsigned*)&g_bar_epoch = target;
                pub = true;
            }
        }
        if (!pub) {
            while ((int)(*(volatile unsigned*)&g_bar_epoch - target) < 0) {}
        }
        __threadfence();
    }
    __syncthreads();
}

// One-time x transpose + fp16 round: x[b][t][64] -> xT[t][b][72-padded]
__global__ void __launch_bounds__(256)
xpose(const float* __restrict__ x) {
    const int t = blockIdx.x;
    for (int i = threadIdx.x; i < 128 * 16; i += 256) {
        int b = i >> 4, j = i & 15;
        float4 v = *(const float4*)(x + ((size_t)b * Tv + t) * 64 + j * 4);
        __half2* dst = (__half2*)(g_xT + (size_t)t * CHUNK_W + b * GW + j * 4);
        dst[0] = __floats2half2_rn(v.x, v.y);
        dst[1] = __floats2half2_rn(v.z, v.w);
    }
}

__global__ void __launch_bounds__(NTHR, 1)
lstm_kernel(const float* __restrict__ w_ih1, const float* __restrict__ w_hh1,
            const float* __restrict__ b_ih1, const float* __restrict__ b_hh1,
            const float* __restrict__ w_ih2, const float* __restrict__ w_hh2,
            const float* __restrict__ b_ih2, const float* __restrict__ b_hh2) {
    extern __shared__ __half smh[];
    __half* chunks = smh;                            // NBUF x [128][GW]
    __half* swh = smh + NBUF * CHUNK_W;              // weights fp16 [32][K1PH|K2PH]
    float* sc = (float*)(swh + 32 * K2PH);           // c-state [128][8]
    float* sb = sc + 128 * 8;                        // fused biases [32]
    float* mbf = sb + 32;                            // NBUF mbarriers
    __shared__ unsigned s_epoch0;

    const int tid = threadIdx.x;
    const bool isL2 = blockIdx.x >= 64;
    const int u0 = (blockIdx.x & 63) * 8;
    const int lane = tid & 31, warp = tid >> 5;
    const int c4 = lane & 3, q = lane >> 2;
    const int r0 = warp * 16 + q, r1 = r0 + 8;
    const int KPH = isL2 ? K2PH : K1PH;
    const int NCH = isL2 ? NCH2 : NCH1;
    const unsigned smem_base = (unsigned)__cvta_generic_to_shared(smh);
    const unsigned mb = (unsigned)__cvta_generic_to_shared(mbf);

    if (tid == 0) {
        s_epoch0 = *(volatile unsigned*)&g_bar_epoch;
#pragma unroll
        for (int b = 0; b < NBUF; b++)
            asm volatile("mbarrier.init.shared.b64 [%0], 1;" :: "r"(mb + b * 8) : "memory");
        asm volatile("fence.proxy.async.shared::cta;" ::: "memory");
    }

    // ---- stage weight slice (fp16) + fused biases ----
    if (!isL2) {
        for (int idx = tid; idx < 32 * K1; idx += NTHR) {
            int r = idx / K1, k = idx - r * K1;
            int j = (r >> 3) * Hv + u0 + (r & 7);
            float wv = (k < DIN) ? w_ih1[j * DIN + k] : w_hh1[(size_t)j * Hv + (k - DIN)];
            swh[r * K1PH + k] = __float2half_rn(wv);
        }
        if (tid < 32) {
            int j = (tid >> 3) * Hv + u0 + (tid & 7);
            sb[tid] = b_ih1[j] + b_hh1[j];
        }
    } else {
        for (int idx = tid; idx < 32 * K2; idx += NTHR) {
            int r = idx >> 10, k = idx & 1023;
            int j = (r >> 3) * Hv + u0 + (r & 7);
            float wv = (k < Hv) ? w_ih2[(size_t)j * Hv + k] : w_hh2[(size_t)j * Hv + (k - Hv)];
            swh[r * K2PH + k] = __float2half_rn(wv);
        }
        if (tid < 32) {
            int j = (tid >> 3) * Hv + u0 + (tid & 7);
            sb[tid] = b_ih2[j] + b_hh2[j];
        }
    }
    for (int i = tid; i < 128 * 8; i += NTHR) sc[i] = 0.0f;

    // ---- zero initial shared state (h1 slot 1, h2 slot 0), as 4B words ----
    {
        unsigned* z1 = (unsigned*)&g_h1[1][0][0][0];
        unsigned* z2 = (unsigned*)g_h2all;
        const int nw = 8 * CHUNK_W / 2;
        for (int idx = blockIdx.x * NTHR + tid; idx < nw; idx += NCTA * NTHR) {
            z1[idx] = 0u;
            z2[idx] = 0u;
        }
    }
    __syncthreads();
    unsigned bar = s_epoch0;
    gridbar(++bar);

    unsigned phbits = 0;
    const int ch = u0 >> 6, colbase = u0 & 63;

    for (int p = 0; p <= Tv; p++) {
        const bool active = isL2 ? (p >= 1) : (p < Tv);
        if (active) {
            const __half* srcA;
            const __half* srcB;
            if (isL2) {
                srcA = &g_h1[(p - 1) & 1][0][0][0];
                srcB = g_h2all + (size_t)(p - 1) * 8 * CHUNK_W;
            } else {
                srcA = g_xT + (size_t)p * CHUNK_W;
                srcB = &g_h1[(p - 1) & 1][0][0][0];
            }
            auto csrc = [&](int c) -> const __half* {
                if (!isL2) return (c == 0) ? srcA : srcB + (size_t)(c - 1) * CHUNK_W;
                return (c < 8) ? srcA + (size_t)c * CHUNK_W : srcB + (size_t)(c - 8) * CHUNK_W;
            };

            float acc[4][4];
#pragma unroll
            for (int g = 0; g < 4; g++) {
                float b0 = sb[g * 8 + 2 * c4], b1 = sb[g * 8 + 2 * c4 + 1];
                acc[g][0] = b0; acc[g][1] = b1; acc[g][2] = b0; acc[g][3] = b1;
            }

            if (tid == 0) {   // prologue: all buffers free (synced last phase)
                const int ni = (NCH < NBUF) ? NCH : NBUF;
                for (int c = 0; c < ni; c++)
                    issue_chunk(smem_base + c * CHUNK_BYTES, csrc(c), mb + c * 8);
            }

            for (int c = 0; c < NCH; c++) {
                const int bsel = c & 7;
                mbar_wait(mb + bsel * 8, (phbits >> bsel) & 1u);
                phbits ^= (1u << bsel);

                const __half* ar0 = chunks + bsel * CHUNK_W + r0 * GW + 2 * c4;
                const __half* ar1 = chunks + bsel * CHUNK_W + r1 * GW + 2 * c4;
                const int kb = c * 64;
#pragma unroll
                for (int kc = 0; kc < 64; kc += 16) {
                    unsigned a0 = *(const unsigned*)(ar0 + kc);
                    unsigned a1 = *(const unsigned*)(ar1 + kc);
                    unsigned a2 = *(const unsigned*)(ar0 + kc + 8);
                    unsigned a3 = *(const unsigned*)(ar1 + kc + 8);
#pragma unroll
                    for (int g = 0; g < 4; g++) {
                        const __half* bp = swh + (g * 8 + q) * KPH + kb + kc + 2 * c4;
                        unsigned b0 = *(const unsigned*)bp;
                        unsigned b1 = *(const unsigned*)(bp + 8);
                        asm volatile(
                            "mma.sync.aligned.m16n8k16.row.col.f32.f16.f16.f32 "
                            "{%0,%1,%2,%3},{%4,%5,%6,%7},{%8,%9},{%0,%1,%2,%3};"
                            : "+f"(acc[g][0]), "+f"(acc[g][1]), "+f"(acc[g][2]), "+f"(acc[g][3])
                            : "r"(a0), "r"(a1), "r"(a2), "r"(a3), "r"(b0), "r"(b1));
                    }
                }
                __syncthreads();                    // all warps done with this buffer
                if (tid == 0 && c + NBUF < NCH)
                    issue_chunk(smem_base + bsel * CHUNK_BYTES, csrc(c + NBUF), mb + bsel * 8);
            }

            // ---- epilogue: nonlinearities, c update (SMEM), fp16 h store ----
            __half* hout = isL2
                ? g_h2all + ((size_t)p * 8 + ch) * CHUNK_W + colbase
                : &g_h1[p & 1][ch][0][colbase];
#pragma unroll
            for (int jj = 0; jj < 2; jj++) {
                int ul = 2 * c4 + jj;
#pragma unroll
                for (int rr = 0; rr < 2; rr++) {
                    int row = rr ? r1 : r0;
                    int qi = rr * 2 + jj;
                    float iv = sigm(acc[0][qi]);
                    float fv = sigm(acc[1][qi]);
                    float gv = tanh_(acc[2][qi]);
                    float ov = sigm(acc[3][qi]);
                    float cn = fv * sc[row * 8 + ul] + iv * gv;
                    sc[row * 8 + ul] = cn;
                    hout[(size_t)row * GW + ul] = __float2half_rn(ov * tanh_(cn));
                }
            }
        }
        gridbar(++bar);
    }
}

// Post-pass: out[b][t][o] = h2(t)[b] . w_out[o] + b_out[o]
__global__ void __launch_bounds__(256)
out_gemm(const float* __restrict__ w_out, const float* __restrict__ b_out,
         float* __restrict__ out) {
    __shared__ __align__(16) float As[32 * OW];  // [k][t]
    __shared__ __align__(16) float Bs[32 * OW];  // [k][o]
    const int b = blockIdx.y;
    const int t0 = blockIdx.x * 64;
    const int tx = threadIdx.x;
    const int to = (tx & 15) * 4;
    const int tt = (tx >> 4) * 4;
    float acc[4][4] = {};
    for (int k0 = 0; k0 < Hv; k0 += 32) {
        for (int i = tx; i < 512; i += 256) {
            int row = i >> 3, kq = (i & 7) * 4;
            const __half* src = g_h2all + ((size_t)(t0 + row + 1) * 8 + (k0 >> 6)) * CHUNK_W
                              + (size_t)b * GW + (k0 & 63) + kq;
            float2 f0 = __half22float2(*(const __half2*)(src));
            float2 f1 = __half22float2(*(const __half2*)(src + 2));
            As[(kq + 0) * OW + row] = f0.x;
            As[(kq + 1) * OW + row] = f0.y;
            As[(kq + 2) * OW + row] = f1.x;
            As[(kq + 3) * OW + row] = f1.y;
        }
        for (int i = tx; i < 512; i += 256) {
            int o = i >> 3, kq = (i & 7) * 4;
            float4 v = *(const float4*)(w_out + (size_t)o * Hv + k0 + kq);
            Bs[(kq + 0) * OW + o] = v.x;
            Bs[(kq + 1) * OW + o] = v.y;
            Bs[(kq + 2) * OW + o] = v.z;
            Bs[(kq + 3) * OW + o] = v.w;
        }
        __syncthreads();
#pragma unroll
        for (int k = 0; k < 32; k++) {
            float4 a = *(const float4*)(As + k * OW + tt);
            float4 w = *(const float4*)(Bs + k * OW + to);
            acc[0][0] = fmaf(a.x, w.x, acc[0][0]); acc[0][1] = fmaf(a.x, w.y, acc[0][1]);
            acc[0][2] = fmaf(a.x, w.z, acc[0][2]); acc[0][3] = fmaf(a.x, w.w, acc[0][3]);
            acc[1][0] = fmaf(a.y, w.x, acc[1][0]); acc[1][1] = fmaf(a.y, w.y, acc[1][1]);
            acc[1][2] = fmaf(a.y, w.z, acc[1][2]); acc[1][3] = fmaf(a.y, w.w, acc[1][3]);
            acc[2][0] = fmaf(a.z, w.x, acc[2][0]); acc[2][1] = fmaf(a.z, w.y, acc[2][1]);
            acc[2][2] = fmaf(a.z, w.z, acc[2][2]); acc[2][3] = fmaf(a.z, w.w, acc[2][3]);
            acc[3][0] = fmaf(a.w, w.x, acc[3][0]); acc[3][1] = fmaf(a.w, w.y, acc[3][1]);
            acc[3][2] = fmaf(a.w, w.z, acc[3][2]); acc[3][3] = fmaf(a.w, w.w, acc[3][3]);
        }
        __syncthreads();
    }
    float bo0 = b_out[to + 0], bo1 = b_out[to + 1], bo2 = b_out[to + 2], bo3 = b_out[to + 3];
#pragma unroll
    for (int i = 0; i < 4; i++) {
        float4 r;
        r.x = acc[i][0] + bo0; r.y = acc[i][1] + bo1;
        r.z = acc[i][2] + bo2; r.w = acc[i][3] + bo3;
        *(float4*)(out + ((size_t)b * Tv + t0 + tt + i) * DOUT + to) = r;
    }
}

extern "C" void kernel_launch(void* const* d_in, const int* in_sizes, int n_in,
                              void* d_out, int out_size) {
    (void)in_sizes; (void)n_in; (void)out_size;
    const float* x     = (const float*)d_in[0];
    const float* w_ih1 = (const float*)d_in[1];
    const float* w_hh1 = (const float*)d_in[2];
    const float* b_ih1 = (const float*)d_in[3];
    const float* b_hh1 = (const float*)d_in[4];
    const float* w_ih2 = (const float*)d_in[5];
    const float* w_hh2 = (const float*)d_in[6];
    const float* b_ih2 = (const float*)d_in[7];
    const float* b_hh2 = (const float*)d_in[8];
    const float* w_out = (const float*)d_in[9];
    const float* b_out = (const float*)d_in[10];

    xpose<<<Tv, 256>>>(x);
    cudaFuncSetAttribute(lstm_kernel, cudaFuncAttributeMaxDynamicSharedMemorySize, SMEM_BYTES);
    lstm_kernel<<<NCTA, NTHR, SMEM_BYTES>>>(w_ih1, w_hh1, b_ih1, b_hh1,
                                            w_ih2, w_hh2, b_ih2, b_hh2);
    out_gemm<<<dim3(Tv / 64, Bv), 256>>>(w_out, b_out, (float*)d_out);
}

// round 9
// speedup vs baseline: 1.1617x; 1.1283x over previous
#include <cuda_runtime.h>
#include <cuda_fp16.h>
#include <cstdint>

#define Bv 128
#define Tv 4096
#define DIN 64
#define Hv 512
#define DOUT 64
#define NCTA 128
#define NTHR 288            // 8 compute warps + 1 producer warp
#define K1 576
#define K2 1024
#define K1PH 584            // weight row stride (halfs) -> conflict-free B-frag LDS
#define K2PH 1032
#define NCH1 9
#define NCH2 16
#define NBUF 8
#define H1D 8               // h1 ring depth (power of 2)
#define SLACK 6             // max L1 lead over L2 (<= H1D-2)
#define GW 72               // chunk row stride (halfs) -> conflict-free A-frag LDS
#define CHUNK_W (128 * GW)
#define CHUNK_BYTES (CHUNK_W * 2)   // 18432
#define OW 68               // out_gemm smem stride (floats)
#define FLG 64              // flag spacing (words) = 256B
#define SMEM_BYTES (NBUF * CHUNK_BYTES + 32 * K2PH * 2 + 128 * 8 * 4 + 32 * 4 + 192)

// Persistent scratch (static __device__: the sanctioned allocation path)
__device__ __half g_xT[(size_t)Tv * CHUNK_W];                 // x transposed, fp16
__device__ __half g_h1[H1D][8][128][GW];                      // layer1 h ring (fp16)
__device__ __half g_h2all[(size_t)(Tv + 1) * 8 * CHUNK_W];    // h2 history; slot 0 = zeros
__device__ unsigned g_flag[NCTA * FLG];                       // per-CTA monotonic phase flags

__device__ __forceinline__ float sigm(float x) { return 1.0f / (1.0f + __expf(-x)); }
__device__ __forceinline__ float tanh_(float x) { return 1.0f - 2.0f / (__expf(2.0f * x) + 1.0f); }

__device__ __forceinline__ unsigned ld_acq(const unsigned* p) {
    unsigned v;
    asm volatile("ld.acquire.gpu.global.b32 %0, [%1];" : "=r"(v) : "l"(p));
    return v;
}
__device__ __forceinline__ void st_rel(unsigned* p, unsigned v) {
    asm volatile("st.release.gpu.global.b32 [%0], %1;" :: "l"(p), "r"(v) : "memory");
}
__device__ __forceinline__ void flag_spin(const unsigned* p, unsigned tgt) {
    while ((int)(ld_acq(p) - tgt) < 0) {}
}
__device__ __forceinline__ void issue_chunk(unsigned sdst, const void* gsrc, unsigned mbar) {
    asm volatile("mbarrier.arrive.expect_tx.shared.b64 _, [%0], %1;"
                 :: "r"(mbar), "r"((unsigned)CHUNK_BYTES) : "memory");
    asm volatile("cp.async.bulk.shared::cta.global.mbarrier::complete_tx::bytes [%0], [%1], %2, [%3];"
                 :: "r"(sdst), "l"(gsrc), "r"((unsigned)CHUNK_BYTES), "r"(mbar) : "memory");
}
__device__ __forceinline__ void mbar_wait(unsigned mbar, unsigned parity) {
    asm volatile(
        "{\n\t.reg .pred P;\n"
        "W%=:\n\t"
        "mbarrier.try_wait.parity.acquire.cta.shared::cta.b64 P, [%0], %1, 0x989680;\n\t"
        "@!P bra W%=;\n\t}"
        :: "r"(mbar), "r"(parity) : "memory");
}
__device__ __forceinline__ void mbar_arrive(unsigned mbar) {
    asm volatile("mbarrier.arrive.shared.b64 _, [%0];" :: "r"(mbar) : "memory");
}

// One-time x transpose + fp16 round: x[b][t][64] -> xT[t][b][72-padded]
__global__ void __launch_bounds__(256)
xpose(const float* __restrict__ x) {
    const int t = blockIdx.x;
    for (int i = threadIdx.x; i < 128 * 16; i += 256) {
        int b = i >> 4, j = i & 15;
        float4 v = *(const float4*)(x + ((size_t)b * Tv + t) * 64 + j * 4);
        __half2* dst = (__half2*)(g_xT + (size_t)t * CHUNK_W + b * GW + j * 4);
        dst[0] = __floats2half2_rn(v.x, v.y);
        dst[1] = __floats2half2_rn(v.z, v.w);
    }
}

__global__ void __launch_bounds__(NTHR, 1)
lstm_kernel(const float* __restrict__ w_ih1, const float* __restrict__ w_hh1,
            const float* __restrict__ b_ih1, const float* __restrict__ b_hh1,
            const float* __restrict__ w_ih2, const float* __restrict__ w_hh2,
            const float* __restrict__ b_ih2, const float* __restrict__ b_hh2) {
    extern __shared__ __half smh[];
    __half* chunks = smh;                            // NBUF x [128][GW]
    __half* swh = smh + NBUF * CHUNK_W;              // weights fp16 [32][K1PH|K2PH]
    float* sc = (float*)(swh + 32 * K2PH);           // c-state [128][8]
    float* sb = sc + 128 * 8;                        // fused biases [32]
    float* mbf = sb + 32;                            // full[8] @ +0, consumed[8] @ +64
    __shared__ unsigned s_e0;

    const int tid = threadIdx.x;
    const bool isL2 = blockIdx.x >= 64;
    const int cl = blockIdx.x & 63;
    const int u0 = cl * 8;
    const int lane = tid & 31, warp = tid >> 5;
    const int c4 = lane & 3, q = lane >> 2;
    const int r0 = warp * 16 + q, r1 = r0 + 8;
    const int KPH = isL2 ? K2PH : K1PH;
    const int NCH = isL2 ? NCH2 : NCH1;
    const unsigned smem_base = (unsigned)__cvta_generic_to_shared(smh);
    const unsigned mb = (unsigned)__cvta_generic_to_shared(mbf);
    const int ch = u0 >> 6, colbase = u0 & 63;

    if (tid == 0) {
        s_e0 = ld_acq(&g_flag[blockIdx.x * FLG]);
#pragma unroll
        for (int b = 0; b < NBUF; b++) {
            asm volatile("mbarrier.init.shared.b64 [%0], 1;" :: "r"(mb + b * 8) : "memory");
            asm volatile("mbarrier.init.shared.b64 [%0], 8;" :: "r"(mb + 64 + b * 8) : "memory");
        }
        asm volatile("fence.proxy.async.shared::cta;" ::: "memory");
    }

    // ---- stage weight slice (fp16) + fused biases ----
    if (!isL2) {
        for (int idx = tid; idx < 32 * K1; idx += NTHR) {
            int r = idx / K1, k = idx - r * K1;
            int j = (r >> 3) * Hv + u0 + (r & 7);
            float wv = (k < DIN) ? w_ih1[j * DIN + k] : w_hh1[(size_t)j * Hv + (k - DIN)];
            swh[r * K1PH + k] = __float2half_rn(wv);
        }
        if (tid < 32) {
            int j = (tid >> 3) * Hv + u0 + (tid & 7);
            sb[tid] = b_ih1[j] + b_hh1[j];
        }
    } else {
        for (int idx = tid; idx < 32 * K2; idx += NTHR) {
            int r = idx >> 10, k = idx & 1023;
            int j = (r >> 3) * Hv + u0 + (r & 7);
            float wv = (k < Hv) ? w_ih2[(size_t)j * Hv + k] : w_hh2[(size_t)j * Hv + (k - Hv)];
            swh[r * K2PH + k] = __float2half_rn(wv);
        }
        if (tid < 32) {
            int j = (tid >> 3) * Hv + u0 + (tid & 7);
            sb[tid] = b_ih2[j] + b_hh2[j];
        }
    }
    for (int i = tid; i < 128 * 8; i += NTHR) sc[i] = 0.0f;

    // ---- zero OWN slice of initial state: h1 ring slot H1D-1 / h2 slot 0 ----
    if (tid < 128) {
        __half z[8];
#pragma unroll
        for (int i = 0; i < 8; i++) z[i] = __float2half(0.0f);
        __half* dst = isL2 ? g_h2all + (size_t)ch * CHUNK_W + (size_t)tid * GW + colbase
                           : &g_h1[H1D - 1][ch][tid][colbase];
        *(uint4*)dst = *(const uint4*)z;
    }
    __syncthreads();
    const unsigned E0 = s_e0;
    if (tid == 0) {
        __threadfence();
        st_rel(&g_flag[blockIdx.x * FLG], E0 + 1);   // init (zeroing) published
    }

    if (warp == 8) {
        // ================= PRODUCER WARP =================
        unsigned gidx = 0;
        for (int p = 0; p <= Tv; p++) {
            const bool active = isL2 ? (p >= 1) : (p < Tv);
            if (!active) continue;
            const unsigned T = E0 + (unsigned)p + 1u;
            if (!isL2 && p >= 6) {   // slack: keep L1 <= SLACK phases ahead of L2
                const unsigned ts = E0 + (unsigned)p - 5u;
                for (int k = lane; k < 64; k += 32) flag_spin(&g_flag[(64 + k) * FLG], ts);
                __syncwarp();
            }
            const __half* srcA;
            const __half* srcB;
            if (isL2) {
                srcA = &g_h1[(p - 1) & (H1D - 1)][0][0][0];
                srcB = g_h2all + (size_t)(p - 1) * 8 * CHUNK_W;
            } else {
                srcA = g_xT + (size_t)p * CHUNK_W;
                srcB = &g_h1[(p - 1) & (H1D - 1)][0][0][0];
            }
            for (int c = 0; c < NCH; c++) {
                const __half* src;
                int pbase = -1;   // producer block base for flag poll (-1 = none)
                if (!isL2) {
                    if (c == 0) { src = srcA; }
                    else { src = srcB + (size_t)(c - 1) * CHUNK_W; pbase = (c - 1) * 8; }
                } else {
                    if (c < 8) { src = srcA + (size_t)c * CHUNK_W; pbase = c * 8; }
                    else { src = srcB + (size_t)(c - 8) * CHUNK_W; pbase = 64 + (c - 8) * 8; }
                }
                if (pbase >= 0) {
                    if (lane < 8) flag_spin(&g_flag[(pbase + lane) * FLG], T);
                    __syncwarp();
                }
                const unsigned s = gidx & (NBUF - 1), m = gidx >> 3;
                if (lane == 0) {
                    if (m >= 1) mbar_wait(mb + 64 + s * 8, (m - 1) & 1u);
                    issue_chunk(smem_base + s * CHUNK_BYTES, src, mb + s * 8);
                }
                __syncwarp();
                gidx++;
            }
        }
    } else {
        // ================= COMPUTE WARPS (0-7) =================
        unsigned phbits = 0, gidx = 0;
        for (int p = 0; p <= Tv; p++) {
            const bool active = isL2 ? (p >= 1) : (p < Tv);
            if (active) {
                float acc[4][4];
#pragma unroll
                for (int g = 0; g < 4; g++) {
                    float b0 = sb[g * 8 + 2 * c4], b1 = sb[g * 8 + 2 * c4 + 1];
                    acc[g][0] = b0; acc[g][1] = b1; acc[g][2] = b0; acc[g][3] = b1;
                }
                for (int c = 0; c < NCH; c++) {
                    const unsigned s = gidx & (NBUF - 1);
                    mbar_wait(mb + s * 8, (phbits >> s) & 1u);
                    phbits ^= (1u << s);

                    const __half* ar0 = chunks + s * CHUNK_W + r0 * GW + 2 * c4;
                    const __half* ar1 = chunks + s * CHUNK_W + r1 * GW + 2 * c4;
                    const int kb = c * 64;
#pragma unroll
                    for (int kc = 0; kc < 64; kc += 16) {
                        unsigned a0 = *(const unsigned*)(ar0 + kc);
                        unsigned a1 = *(const unsigned*)(ar1 + kc);
                        unsigned a2 = *(const unsigned*)(ar0 + kc + 8);
                        unsigned a3 = *(const unsigned*)(ar1 + kc + 8);
#pragma unroll
                        for (int g = 0; g < 4; g++) {
                            const __half* bp = swh + (g * 8 + q) * KPH + kb + kc + 2 * c4;
                            unsigned b0 = *(const unsigned*)bp;
                            unsigned b1 = *(const unsigned*)(bp + 8);
                            asm volatile(
                                "mma.sync.aligned.m16n8k16.row.col.f32.f16.f16.f32 "
                                "{%0,%1,%2,%3},{%4,%5,%6,%7},{%8,%9},{%0,%1,%2,%3};"
                                : "+f"(acc[g][0]), "+f"(acc[g][1]), "+f"(acc[g][2]), "+f"(acc[g][3])
                                : "r"(a0), "r"(a1), "r"(a2), "r"(a3), "r"(b0), "r"(b1));
                        }
                    }
                    if (lane == 0) mbar_arrive(mb + 64 + s * 8);   // warp done with buffer
                    gidx++;
                }

                // ---- epilogue: nonlinearities, c update (SMEM), fp16 h store ----
                __half* hout = isL2
                    ? g_h2all + ((size_t)p * 8 + ch) * CHUNK_W + colbase
                    : &g_h1[p & (H1D - 1)][ch][0][colbase];
#pragma unroll
                for (int jj = 0; jj < 2; jj++) {
                    int ul = 2 * c4 + jj;
#pragma unroll
                    for (int rr = 0; rr < 2; rr++) {
                        int row = rr ? r1 : r0;
                        int qi = rr * 2 + jj;
                        float iv = sigm(acc[0][qi]);
                        float fv = sigm(acc[1][qi]);
                        float gv = tanh_(acc[2][qi]);
                        float ov = sigm(acc[3][qi]);
                        float cn = fv * sc[row * 8 + ul] + iv * gv;
                        sc[row * 8 + ul] = cn;
                        hout[(size_t)row * GW + ul] = __float2half_rn(ov * tanh_(cn));
                    }
                }
            }
            // compute-only barrier (producer excluded), then publish phase flag
            asm volatile("bar.sync 1, 256;" ::: "memory");
            if (tid == 0) {
                __threadfence();
                st_rel(&g_flag[blockIdx.x * FLG], E0 + (unsigned)p + 2u);
            }
        }
    }
}

// Post-pass: out[b][t][o] = h2(t)[b] . w_out[o] + b_out[o]
__global__ void __launch_bounds__(256)
out_gemm(const float* __restrict__ w_out, const float* __restrict__ b_out,
         float* __restrict__ out) {
    __shared__ __align__(16) float As[32 * OW];  // [k][t]
    __shared__ __align__(16) float Bs[32 * OW];  // [k][o]
    const int b = blockIdx.y;
    const int t0 = blockIdx.x * 64;
    const int tx = threadIdx.x;
    const int to = (tx & 15) * 4;
    const int tt = (tx >> 4) * 4;
    float acc[4][4] = {};
    for (int k0 = 0; k0 < Hv; k0 += 32) {
        for (int i = tx; i < 512; i += 256) {
            int row = i >> 3, kq = (i & 7) * 4;
            const __half* src = g_h2all + ((size_t)(t0 + row + 1) * 8 + (k0 >> 6)) * CHUNK_W
                              + (size_t)b * GW + (k0 & 63) + kq;
            float2 f0 = __half22float2(*(const __half2*)(src));
            float2 f1 = __half22float2(*(const __half2*)(src + 2));
            As[(kq + 0) * OW + row] = f0.x;
            As[(kq + 1) * OW + row] = f0.y;
            As[(kq + 2) * OW + row] = f1.x;
            As[(kq + 3) * OW + row] = f1.y;
        }
        for (int i = tx; i < 512; i += 256) {
            int o = i >> 3, kq = (i & 7) * 4;
            float4 v = *(const float4*)(w_out + (size_t)o * Hv + k0 + kq);
            Bs[(kq + 0) * OW + o] = v.x;
            Bs[(kq + 1) * OW + o] = v.y;
            Bs[(kq + 2) * OW + o] = v.z;
            Bs[(kq + 3) * OW + o] = v.w;
        }
        __syncthreads();
#pragma unroll
        for (int k = 0; k < 32; k++) {
            float4 a = *(const float4*)(As + k * OW + tt);
            float4 w = *(const float4*)(Bs + k * OW + to);
            acc[0][0] = fmaf(a.x, w.x, acc[0][0]); acc[0][1] = fmaf(a.x, w.y, acc[0][1]);
            acc[0][2] = fmaf(a.x, w.z, acc[0][2]); acc[0][3] = fmaf(a.x, w.w, acc[0][3]);
            acc[1][0] = fmaf(a.y, w.x, acc[1][0]); acc[1][1] = fmaf(a.y, w.y, acc[1][1]);
            acc[1][2] = fmaf(a.y, w.z, acc[1][2]); acc[1][3] = fmaf(a.y, w.w, acc[1][3]);
            acc[2][0] = fmaf(a.z, w.x, acc[2][0]); acc[2][1] = fmaf(a.z, w.y, acc[2][1]);
            acc[2][2] = fmaf(a.z, w.z, acc[2][2]); acc[2][3] = fmaf(a.z, w.w, acc[2][3]);
            acc[3][0] = fmaf(a.w, w.x, acc[3][0]); acc[3][1] = fmaf(a.w, w.y, acc[3][1]);
            acc[3][2] = fmaf(a.w, w.z, acc[3][2]); acc[3][3] = fmaf(a.w, w.w, acc[3][3]);
        }
        __syncthreads();
    }
    float bo0 = b_out[to + 0], bo1 = b_out[to + 1], bo2 = b_out[to + 2], bo3 = b_out[to + 3];
#pragma unroll
    for (int i = 0; i < 4; i++) {
        float4 r;
        r.x = acc[i][0] + bo0; r.y = acc[i][1] + bo1;
        r.z = acc[i][2] + bo2; r.w = acc[i][3] + bo3;
        *(float4*)(out + ((size_t)b * Tv + t0 + tt + i) * DOUT + to) = r;
    }
}

extern "C" void kernel_launch(void* const* d_in, const int* in_sizes, int n_in,
                              void* d_out, int out_size) {
    (void)in_sizes; (void)n_in; (void)out_size;
    const float* x     = (const float*)d_in[0];
    const float* w_ih1 = (const float*)d_in[1];
    const float* w_hh1 = (const float*)d_in[2];
    const float* b_ih1 = (const float*)d_in[3];
    const float* b_hh1 = (const float*)d_in[4];
    const float* w_ih2 = (const float*)d_in[5];
    const float* w_hh2 = (const float*)d_in[6];
    const float* b_ih2 = (const float*)d_in[7];
    const float* b_hh2 = (const float*)d_in[8];
    const float* w_out = (const float*)d_in[9];
    const float* b_out = (const float*)d_in[10];

    xpose<<<Tv, 256>>>(x);
    cudaFuncSetAttribute(lstm_kernel, cudaFuncAttributeMaxDynamicSharedMemorySize, SMEM_BYTES);
    lstm_kernel<<<NCTA, NTHR, SMEM_BYTES>>>(w_ih1, w_hh1, b_ih1, b_hh1,
                                            w_ih2, w_hh2, b_ih2, b_hh2);
    out_gemm<<<dim3(Tv / 64, Bv), 256>>>(w_out, b_out, (float*)d_out);
}